// round 17
// baseline (speedup 1.0000x reference)
#include <cuda_runtime.h>
#include <cuda_fp16.h>
#include <cstdint>
#include <cstddef>

typedef __half h16;

// ============================ helpers ============================
__device__ __forceinline__ uint32_t smem_u32(const void* p) {
    uint32_t a;
    asm("{ .reg .u64 t; cvta.to.shared.u64 t, %1; cvt.u32.u64 %0, t; }" : "=r"(a) : "l"(p));
    return a;
}
__device__ __forceinline__ void ldsm4(uint32_t& r0, uint32_t& r1, uint32_t& r2, uint32_t& r3,
                                      uint32_t addr) {
    asm volatile("ldmatrix.sync.aligned.m8n8.x4.shared.b16 {%0,%1,%2,%3}, [%4];"
                 : "=r"(r0), "=r"(r1), "=r"(r2), "=r"(r3) : "r"(addr));
}
__device__ __forceinline__ void mma16816(float c[4], const uint32_t a[4], const uint32_t b[2]) {
    asm volatile(
        "mma.sync.aligned.m16n8k16.row.col.f32.f16.f16.f32 "
        "{%0,%1,%2,%3}, {%4,%5,%6,%7}, {%8,%9}, {%0,%1,%2,%3};"
        : "+f"(c[0]), "+f"(c[1]), "+f"(c[2]), "+f"(c[3])
        : "r"(a[0]), "r"(a[1]), "r"(a[2]), "r"(a[3]), "r"(b[0]), "r"(b[1]));
}
// 16B async copy, zero-fill when srcsize==0
__device__ __forceinline__ void cp16(uint32_t dst, const void* src, uint32_t srcsize) {
    asm volatile("cp.async.cg.shared.global [%0], [%1], 16, %2;"
                 :: "r"(dst), "l"(src), "r"(srcsize) : "memory");
}
#define CP_COMMIT() asm volatile("cp.async.commit_group;" ::: "memory")
#define CP_WAIT(n)  asm volatile("cp.async.wait_group %0;" :: "n"(n) : "memory")

// smem tile pitch: 72 h16 (144 B) -> row stride 36 words -> ldmatrix conflict-free
static constexpr int PITCH = 72;
static constexpr int ATILE_B = 128 * PITCH * 2;   // 18432 bytes per 128x64 tile

// ============================ scratch ============================
__device__ h16 g_x1[(size_t)64 * 112 * 112 * 64];
__device__ h16 g_x2[(size_t)64 * 56 * 56 * 128];
__device__ h16 g_x3[(size_t)64 * 28 * 28 * 256];
__device__ h16 g_x4[(size_t)64 * 14 * 14 * 512];
__device__ h16 g_w1[64 * 32];               // conv1 padded [co][32]
__device__ h16 g_w2[9 * 128 * 64];          // [t][co][ci]
__device__ h16 g_w3[9 * 256 * 128];
__device__ h16 g_w4[9 * 512 * 256];
__device__ float g_sent[64 * 512];

// ============================ merged weight prep ============================
__global__ void wprep_all_k(const float* __restrict__ cw1, const float* __restrict__ cw2,
                            const float* __restrict__ cw3, const float* __restrict__ cw4,
                            h16* __restrict__ w1, h16* __restrict__ w2,
                            h16* __restrict__ w3, h16* __restrict__ w4) {
    int idx = blockIdx.x * 256 + threadIdx.x;
    if (idx < 2048) {
        int co = idx >> 5, k = idx & 31;
        w1[idx] = __float2half_rn((k < 27) ? cw1[co * 27 + k] : 0.0f);
        return;
    }
    idx -= 2048;
    const float* src; h16* dst; int COUT, CIN;
    if (idx < 73728)        { src = cw2; dst = w2; COUT = 128; CIN = 64; }
    else if (idx < 73728 + 294912) { idx -= 73728; src = cw3; dst = w3; COUT = 256; CIN = 128; }
    else                    { idx -= 73728 + 294912; if (idx >= 1179648) return;
                              src = cw4; dst = w4; COUT = 512; CIN = 256; }
    int co = idx / (CIN * 9);
    int rem = idx - co * (CIN * 9);
    int ci = rem / 9, t = rem - ci * 9;
    dst[(t * COUT + co) * CIN + ci] = __float2half_rn(src[idx]);
}

// ============================ warp-level GEMM core ============================
template <int NFRAG, int KSTEPS>
__device__ __forceinline__ void chunk_mma(uint32_t sbA, uint32_t sbB,
                                          int lane, int warpM, int warpN,
                                          float (&c)[2][NFRAG][4]) {
    const int arow = warpM * 32 + (lane & 15);
    const int akoff = (lane >> 4) * 8;
    const int brow = warpN * (NFRAG * 8) + (lane & 7) + ((lane >> 3) & 1) * 8;
    const int bkoff = (lane >> 4) * 8;
#pragma unroll
    for (int ks = 0; ks < KSTEPS; ks++) {
        const int k0 = ks * 16;
        uint32_t ah[2][4];
#pragma unroll
        for (int i = 0; i < 2; i++) {
            const uint32_t aoff = (((arow + i * 16) * PITCH) + k0 + akoff) * 2;
            ldsm4(ah[i][0], ah[i][1], ah[i][2], ah[i][3], sbA + aoff);
        }
        uint32_t bh[NFRAG][2];
#pragma unroll
        for (int j2 = 0; j2 < NFRAG / 2; j2++) {
            const uint32_t boff = (((brow + j2 * 16) * PITCH) + k0 + bkoff) * 2;
            uint32_t r0, r1, r2, r3;
            ldsm4(r0, r1, r2, r3, sbB + boff);
            bh[2 * j2][0] = r0; bh[2 * j2][1] = r2;
            bh[2 * j2 + 1][0] = r1; bh[2 * j2 + 1][1] = r3;
        }
#pragma unroll
        for (int i = 0; i < 2; i++)
#pragma unroll
            for (int j = 0; j < NFRAG; j++)
                mma16816(c[i][j], ah[i], bh[j]);
    }
}

// epilogue: bias + relu + cvt -> NHWC fp16
template <int NFRAG, int COUT>
__device__ __forceinline__ void epilogue(float (&c)[2][NFRAG][4], const float* __restrict__ bias,
                                         int tile0, int cob, int lane, int warpM, int warpN,
                                         h16* __restrict__ y) {
#pragma unroll
    for (int i = 0; i < 2; i++) {
        const int r0 = tile0 + warpM * 32 + i * 16 + (lane >> 2);
#pragma unroll
        for (int j = 0; j < NFRAG; j++) {
            const int col = cob + warpN * (NFRAG * 8) + j * 8 + (lane & 3) * 2;
            const float b0 = bias[col], b1 = bias[col + 1];
#pragma unroll
            for (int h = 0; h < 2; h++) {
                const int r = r0 + h * 8;
                float v0 = c[i][j][2 * h + 0] + b0; if (v0 < 0.0f) v0 = 0.0f;
                float v1 = c[i][j][2 * h + 1] + b1; if (v1 < 0.0f) v1 = 0.0f;
                __half2 p;
                p.x = __float2half_rn(v0); p.y = __float2half_rn(v1);
                *(__half2*)(y + (size_t)r * COUT + col) = p;
            }
        }
    }
}

// ============================ conv2/3/4: implicit GEMM, cp.async pipeline ============================
// STAGES=3: single-sync loop (restage target consumed 2 chunks ago)
// STAGES=2: classic double-buffer with 2 syncs per chunk
template <int CIN, int COUT, int HIN, int WIN, int NTILE, int MINCTA, int STAGES>
__global__ void __launch_bounds__(256, MINCTA)
convmm_k(const h16* __restrict__ x, const h16* __restrict__ wt,
         const float* __restrict__ bias, h16* __restrict__ y) {
    constexpr int HOUT = HIN / 2, WOUT = WIN / 2;
    constexpr int CPT = CIN / 64;
    constexpr int NCH = 9 * CPT;
    constexpr int NFRAG = NTILE / 16;
    constexpr int BSLOTS = NTILE / 32;
    constexpr int BUF_B = ATILE_B + NTILE * PITCH * 2;   // A tile + B tile

    extern __shared__ char sb[];
    const uint32_t sb32 = smem_u32(sb);

    const int tid = threadIdx.x, lane = tid & 31, wid = tid >> 5;
    const int warpM = wid >> 1, warpN = wid & 1;
    const int tile0 = blockIdx.x * 128;
    const int cob = blockIdx.y * NTILE;

    const int c16 = tid & 7;
    int baseoff[4]; bool xe[4], ye[4];
#pragma unroll
    for (int r4 = 0; r4 < 4; r4++) {
        const int row = (tid >> 3) + 32 * r4;
        const int s = tile0 + row;
        const int n = s / (HOUT * WOUT);
        const int rem = s - n * (HOUT * WOUT);
        const int y2 = rem / WOUT;
        const int x2 = rem - y2 * WOUT;
        baseoff[r4] = ((n * HIN + 2 * y2) * WIN + 2 * x2) * CIN;
        xe[r4] = (2 * x2 + 2 >= WIN);
        ye[r4] = (2 * y2 + 2 >= HIN);
    }

    auto stage = [&](int ch) {
        const int t = ch / CPT;
        const int cb = (ch - t * CPT) * 64;
        const int ky = t / 3, kx = t - ky * 3;
        const uint32_t base = sb32 + (ch % STAGES) * BUF_B;
#pragma unroll
        for (int r4 = 0; r4 < 4; r4++) {
            const int row = (tid >> 3) + 32 * r4;
            const uint32_t soff = (row * PITCH + c16 * 8) * 2;
            const bool valid = !((kx == 2 && xe[r4]) || (ky == 2 && ye[r4]));
            const size_t src = (size_t)baseoff[r4] + (ky * WIN + kx) * CIN + cb + c16 * 8;
            cp16(base + soff, x + src, valid ? 16u : 0u);
            if (r4 < BSLOTS) {
                const size_t wsrc = ((size_t)t * COUT + cob + row) * CIN + cb + c16 * 8;
                cp16(base + ATILE_B + soff, wt + wsrc, 16u);
            }
        }
        CP_COMMIT();
    };

    float c[2][NFRAG][4];
#pragma unroll
    for (int i = 0; i < 2; i++)
#pragma unroll
        for (int j = 0; j < NFRAG; j++)
#pragma unroll
            for (int q = 0; q < 4; q++) c[i][j][q] = 0.0f;

    if (STAGES == 3) {
        // 3-buffer, one sync per chunk
        stage(0);
        if (NCH > 1) stage(1);
        for (int ch = 0; ch < NCH; ch++) {
            if (ch + 1 < NCH) { CP_WAIT(1); } else { CP_WAIT(0); }
            __syncthreads();   // chunk ch visible; readers of ch-1 (buffer (ch+2)%3) done
            if (ch + 2 < NCH) stage(ch + 2);
            const uint32_t base = sb32 + (ch % 3) * BUF_B;
            chunk_mma<NFRAG, 4>(base, base + ATILE_B, lane, warpM, warpN, c);
        }
    } else {
        // 2-buffer, two syncs per chunk
        stage(0);
        for (int ch = 0; ch < NCH; ch++) {
            if (ch + 1 < NCH) { stage(ch + 1); CP_WAIT(1); }
            else              { CP_WAIT(0); }
            __syncthreads();
            const uint32_t base = sb32 + (ch & 1) * BUF_B;
            chunk_mma<NFRAG, 4>(base, base + ATILE_B, lane, warpM, warpN, c);
            __syncthreads();
        }
    }

    epilogue<NFRAG, COUT>(c, bias, tile0, cob, lane, warpM, warpN, y);
}

// ============================ conv1: implicit GEMM, K=27 (padded 32), 4 CTAs/SM ============================
__global__ void __launch_bounds__(256, 4)
conv1mm_k(const float* __restrict__ images,
          const h16* __restrict__ wh,
          const float* __restrict__ bias,
          h16* __restrict__ y) {
    constexpr int HOUT = 112, WOUT = 112, HIN = 224, WIN = 224;
    constexpr int NFRAG = 4;

    extern __shared__ char sb[];
    const uint32_t sb32 = smem_u32(sb);
    const uint32_t oA = 0, oB = ATILE_B;

    const int tid = threadIdx.x, lane = tid & 31, wid = tid >> 5;
    const int warpM = wid >> 1, warpN = wid & 1;
    const int tile0 = blockIdx.x * 128;

    // A staging: thread owns (row, k-half); vectorized tap loads (float2 for kx=0,1
    // + scalar for kx=2), register-pack 16 taps, 2x STS.128 (conflict-free).
    {
        const int g = wid >> 2;                 // 0: k0..15, 1: k16..31
        const int row = ((wid & 3) << 5) + lane;
        const int s = tile0 + row;
        const int n = s / (HOUT * WOUT);
        const int rem = s - n * (HOUT * WOUT);
        const int y2 = rem / WOUT;
        const int x2 = rem - y2 * WOUT;
        const float* p0 = images + ((size_t)(n * 3) * HIN + 2 * y2) * WIN + 2 * x2;
        const bool xok = (x2 < 111);
        const bool yok = (y2 < 111);
        union { h16 h[16]; uint4 u[2]; } pk;
#pragma unroll
        for (int i = 0; i < 16; i++) pk.h[i] = __float2half_rn(0.0f);

        auto fill = [&](const int klo) {
#pragma unroll
            for (int ci = 0; ci < 3; ci++)
#pragma unroll
                for (int ky = 0; ky < 3; ky++) {
                    const int kb = ci * 9 + ky * 3;
                    if (kb + 2 >= klo && kb < klo + 16) {
                        const bool yv = (ky < 2) || yok;
                        const float* gp = p0 + (size_t)ci * (HIN * WIN) + ky * WIN;
                        float2 a = make_float2(0.0f, 0.0f);
                        if (yv) a = *(const float2*)gp;
                        float b2 = 0.0f;
                        if (yv && xok) b2 = gp[2];
                        if (kb >= klo && kb < klo + 16)         pk.h[kb - klo]     = __float2half_rn(a.x);
                        if (kb + 1 >= klo && kb + 1 < klo + 16) pk.h[kb + 1 - klo] = __float2half_rn(a.y);
                        if (kb + 2 >= klo && kb + 2 < klo + 16) pk.h[kb + 2 - klo] = __float2half_rn(b2);
                    }
                }
        };
        if (g == 0) fill(0); else fill(16);

        char* dst = sb + oA + row * (PITCH * 2) + g * 32;
        *(uint4*)dst = pk.u[0];
        *(uint4*)(dst + 16) = pk.u[1];
    }
    // B staging: 64 couts x 32 k (w1 is [co][32])
    if (tid < 256) {
        const int r = tid >> 2, c16 = tid & 3;
        *(uint4*)(sb + oB + (r * PITCH + c16 * 8) * 2) = *(const uint4*)(wh + r * 32 + c16 * 8);
    }
    __syncthreads();

    float c[2][NFRAG][4];
#pragma unroll
    for (int i = 0; i < 2; i++)
#pragma unroll
        for (int j = 0; j < NFRAG; j++)
#pragma unroll
            for (int q = 0; q < 4; q++) c[i][j][q] = 0.0f;

    chunk_mma<NFRAG, 2>(sb32 + oA, sb32 + oB, lane, warpM, warpN, c);

    epilogue<NFRAG, 64>(c, bias, tile0, 0, lane, warpM, warpN, y);
}

// ============================ fused text branch: embed mean + rnn linear ============================
__global__ void __launch_bounds__(512)
text_k(const int* __restrict__ seq, const int* __restrict__ len,
       const float* __restrict__ emb,
       const float* __restrict__ rnn_w, const float* __restrict__ rnn_b,
       float* __restrict__ sent) {
    const int b = blockIdx.x;
    const int tid = threadIdx.x;   // 0..511
    __shared__ int s_idx[128];
    __shared__ float s_m[512];
    if (tid < 128) s_idx[tid] = seq[b * 128 + tid];
    __syncthreads();
    const int L = len[b];
    float acc = 0.0f;
    for (int s = 0; s < L; s++) acc += emb[(size_t)s_idx[s] * 512 + tid];
    s_m[tid] = acc / (float)L;
    __syncthreads();
    float o = rnn_b[tid];
    for (int k = 0; k < 512; k++) o = fmaf(s_m[k], rnn_w[(size_t)k * 512 + tid], o);
    sent[(size_t)b * 512 + tid] = o;
}

// ============================ fused head: pool + fc1(concat) + fc2 + clf ============================
__global__ void __launch_bounds__(512)
head_k(const h16* __restrict__ x4, const float* __restrict__ sent,
       const float* __restrict__ fc1_w, const float* __restrict__ fc1_b,
       const float* __restrict__ fc2_w, const float* __restrict__ fc2_b,
       const float* __restrict__ clf_w, const float* __restrict__ clf_b,
       float* __restrict__ out) {
    const int b = blockIdx.x;
    const int tid = threadIdx.x;   // 0..511
    __shared__ float s_a[512], s_s[512], s_h1[512], s_h2[512];

    // pool: channel tid, mean over 196 positions
    const h16* p = x4 + (size_t)b * 196 * 512 + tid;
    float sum = 0.0f;
    for (int i = 0; i < 196; i++) sum += __half2float(p[(size_t)i * 512]);
    s_a[tid] = sum * (1.0f / 196.0f);
    s_s[tid] = sent[(size_t)b * 512 + tid];
    __syncthreads();

    // fc1 (concat fused) + relu
    float a1 = fc1_b[tid];
    for (int k = 0; k < 512; k++) a1 = fmaf(s_a[k], fc1_w[(size_t)k * 512 + tid], a1);
    for (int k = 0; k < 512; k++) a1 = fmaf(s_s[k], fc1_w[(size_t)(512 + k) * 512 + tid], a1);
    s_h1[tid] = a1 > 0.0f ? a1 : 0.0f;
    __syncthreads();

    // fc2 + relu
    float a2 = fc2_b[tid];
    for (int k = 0; k < 512; k++) a2 = fmaf(s_h1[k], fc2_w[(size_t)k * 512 + tid], a2);
    s_h2[tid] = a2 > 0.0f ? a2 : 0.0f;
    __syncthreads();

    // clf (N=1000)
    for (int n = tid; n < 1000; n += 512) {
        float o = clf_b[n];
        for (int k = 0; k < 512; k++) o = fmaf(s_h2[k], clf_w[(size_t)k * 1000 + n], o);
        out[(size_t)b * 1000 + n] = o;
    }
}

// ============================ launch ============================
extern "C" void kernel_launch(void* const* d_in, const int* in_sizes, int n_in,
                              void* d_out, int out_size) {
    const float* images = (const float*)d_in[0];
    const int*   seq    = (const int*)d_in[1];
    const int*   len    = (const int*)d_in[2];
    const float* emb    = (const float*)d_in[4];
    const float* cw1 = (const float*)d_in[5],  *cb1 = (const float*)d_in[6];
    const float* cw2 = (const float*)d_in[7],  *cb2 = (const float*)d_in[8];
    const float* cw3 = (const float*)d_in[9],  *cb3 = (const float*)d_in[10];
    const float* cw4 = (const float*)d_in[11], *cb4 = (const float*)d_in[12];
    const float* rnn_w = (const float*)d_in[13], *rnn_b = (const float*)d_in[14];
    const float* fc1_w = (const float*)d_in[15], *fc1_b = (const float*)d_in[16];
    const float* fc2_w = (const float*)d_in[17], *fc2_b = (const float*)d_in[18];
    const float* clf_w = (const float*)d_in[19], *clf_b = (const float*)d_in[20];
    float* out = (float*)d_out;

    h16 *x1, *x2, *x3, *x4, *w1, *w2, *w3, *w4;
    float *sent;
    cudaGetSymbolAddress((void**)&x1, g_x1); cudaGetSymbolAddress((void**)&x2, g_x2);
    cudaGetSymbolAddress((void**)&x3, g_x3); cudaGetSymbolAddress((void**)&x4, g_x4);
    cudaGetSymbolAddress((void**)&w1, g_w1); cudaGetSymbolAddress((void**)&w2, g_w2);
    cudaGetSymbolAddress((void**)&w3, g_w3); cudaGetSymbolAddress((void**)&w4, g_w4);
    cudaGetSymbolAddress((void**)&sent, g_sent);

    const int smem2 = 3 * (ATILE_B + 128 * PITCH * 2);   // 110592 (3-stage, NTILE=128, 2 CTAs/SM)
    const int smem34 = 2 * (ATILE_B + 64 * PITCH * 2);   // 55296 (2-stage, NTILE=64, 3 CTAs/SM)
    const int smem1  = ATILE_B + 64 * PITCH * 2;         // 27648 (single, conv1)
    cudaFuncSetAttribute(conv1mm_k, cudaFuncAttributeMaxDynamicSharedMemorySize, smem1);
    cudaFuncSetAttribute(convmm_k<64, 128, 112, 112, 128, 2, 3>, cudaFuncAttributeMaxDynamicSharedMemorySize, smem2);
    cudaFuncSetAttribute(convmm_k<128, 256, 56, 56, 64, 3, 2>,   cudaFuncAttributeMaxDynamicSharedMemorySize, smem34);
    cudaFuncSetAttribute(convmm_k<256, 512, 28, 28, 64, 3, 2>,   cudaFuncAttributeMaxDynamicSharedMemorySize, smem34);

    // 1: text branch (fused)
    text_k<<<64, 512>>>(seq, len, emb, rnn_w, rnn_b, sent);

    // 2: merged weight prep
    wprep_all_k<<<(2048 + 73728 + 294912 + 1179648 + 255) / 256, 256>>>(
        cw1, cw2, cw3, cw4, w1, w2, w3, w4);

    // 3-6: vision branch
    conv1mm_k<<<6272, 256, smem1>>>(images, w1, cb1, x1);
    convmm_k<64, 128, 112, 112, 128, 2, 3><<<dim3(1568, 1), 256, smem2>>>(x1, w2, cb2, x2);
    convmm_k<128, 256, 56, 56, 64, 3, 2><<<dim3(392, 4), 256, smem34>>>(x2, w3, cb3, x3);
    convmm_k<256, 512, 28, 28, 64, 3, 2><<<dim3(98, 8), 256, smem34>>>(x3, w4, cb4, x4);

    // 7: fused head (pool + fc1 + fc2 + clf)
    head_k<<<64, 512>>>(x4, sent, fc1_w, fc1_b, fc2_w, fc2_b, clf_w, clf_b, out);
}